// round 11
// baseline (speedup 1.0000x reference)
#include <cuda_runtime.h>
#include <cuda_fp16.h>
#include <cstdint>

// ================= problem dims =================
static constexpr int M_TOTAL = 16384;   // B*S = 4*4096
static constexpr int N_TOTAL = 12288;   // 3*E
static constexpr int K_TOTAL = 4096;    // E
static constexpr int TILE_M  = 128;
static constexpr int TILE_N  = 128;
static constexpr int TILE_K  = 64;      // 64 halves = 128B rows (swizzle atom)
static constexpr int STAGES  = 3;
static constexpr int KCHUNKS = K_TOTAL / TILE_K;  // 64
static constexpr int MT = M_TOTAL / TILE_M;       // 128
static constexpr int NT = N_TOTAL / TILE_N;       // 96
static constexpr int GROUP_M = 32;

static constexpr int A_TILE_BYTES = TILE_M * TILE_K * 2;   // 16384
static constexpr int B_TILE_BYTES = TILE_N * TILE_K * 2;   // 16384
static constexpr int STAGE_BYTES  = A_TILE_BYTES + B_TILE_BYTES; // 32768
static constexpr int SMEM_BYTES   = STAGES * STAGE_BYTES;        // 98304

// fp16 copies of the inputs (RN). fp16 mantissa == tf32 mantissa (10 bits).
__device__ __half g_Xh[(size_t)M_TOTAL * K_TOTAL];
__device__ __half g_Wh[(size_t)N_TOTAL * K_TOTAL];

// ================= helpers =================
__device__ __forceinline__ uint32_t smem_u32(const void* p) {
    uint32_t a;
    asm("{ .reg .u64 t; cvta.to.shared.u64 t, %1; cvt.u32.u64 %0, t; }"
        : "=r"(a) : "l"(p));
    return a;
}

__device__ __forceinline__ void cp_async16(uint32_t dst, const void* src) {
    asm volatile("cp.async.cg.shared.global [%0], [%1], 16;" :: "r"(dst), "l"(src));
}
__device__ __forceinline__ void cp_commit() {
    asm volatile("cp.async.commit_group;" ::: "memory");
}
template <int N>
__device__ __forceinline__ void cp_wait() {
    asm volatile("cp.async.wait_group %0;" :: "n"(N) : "memory");
}

// 128B-block swizzle: XOR 16B-unit index with low 3 row bits
#define SWZ(o) ((o) ^ (((o) >> 3) & 0x70))

// ldmatrix x4: four 8x8 b16 matrices, per-lane row addresses
__device__ __forceinline__ void ldsm_x4(uint32_t& r0, uint32_t& r1,
                                        uint32_t& r2, uint32_t& r3,
                                        uint32_t addr) {
    asm volatile("ldmatrix.sync.aligned.m8n8.x4.shared.b16 {%0,%1,%2,%3}, [%4];"
                 : "=r"(r0), "=r"(r1), "=r"(r2), "=r"(r3) : "r"(addr));
}

// fp16 MMA, fp32 accumulate (sm_80+, legal on plain sm_103 target)
__device__ __forceinline__ void mma_f16(float* c, const uint32_t* a,
                                        const uint32_t* b) {
    asm volatile(
        "mma.sync.aligned.m16n8k16.row.col.f32.f16.f16.f32 "
        "{%0,%1,%2,%3}, {%4,%5,%6,%7}, {%8,%9}, {%0,%1,%2,%3};"
        : "+f"(c[0]), "+f"(c[1]), "+f"(c[2]), "+f"(c[3])
        : "r"(a[0]), "r"(a[1]), "r"(a[2]), "r"(a[3]),
          "r"(b[0]), "r"(b[1]));
}

// streaming 8B store (output is write-once, never re-read by this grid)
__device__ __forceinline__ void stg_cs_v2(float* p, float x, float y) {
    asm volatile("st.global.cs.v2.f32 [%0], {%1, %2};"
                 :: "l"(p), "f"(x), "f"(y) : "memory");
}

// ================= fp32 -> fp16 RN pre-pass (both arrays, one launch) =======
static constexpr int NX4 = M_TOTAL * (K_TOTAL / 4);   // X float4 count
static constexpr int NW4 = N_TOTAL * (K_TOTAL / 4);   // W float4 count

__global__ void __launch_bounds__(256)
cvt_both_kernel(const float* __restrict__ X, const float* __restrict__ W) {
    int i = blockIdx.x * blockDim.x + threadIdx.x;
    int stride = gridDim.x * blockDim.x;
    for (; i < NX4 + NW4; i += stride) {
        const float4* s;
        __half* dst;
        int k;
        if (i < NX4) { s = (const float4*)X; dst = g_Xh; k = i; }
        else         { s = (const float4*)W; dst = g_Wh; k = i - NX4; }
        float4 v = s[k];
        __half2 h0 = __floats2half2_rn(v.x, v.y);
        __half2 h1 = __floats2half2_rn(v.z, v.w);
        uint2 pack = make_uint2(*(uint32_t*)&h0, *(uint32_t*)&h1);
        *(uint2*)(dst + (size_t)k * 4) = pack;
    }
}

// ================= GEMM kernel =================
__global__ void __launch_bounds__(256, 2)
qkv_gemm_kernel(float* __restrict__ out) {
    extern __shared__ __align__(1024) char smem[];
    const uint32_t sb = smem_u32(smem);
    const int tid = threadIdx.x;
    const int wid = tid >> 5;
    const int lid = tid & 31;

    // ---- tile mapping (grouped raster for L2 reuse) ----
    int bid = blockIdx.x;
    const int TPG = GROUP_M * NT;
    int g   = bid / TPG;
    int rem = bid % TPG;
    int m0g = g * GROUP_M;
    int rows = (MT - m0g) < GROUP_M ? (MT - m0g) : GROUP_M;
    int mtile = m0g + rem % rows;
    int ntile = rem / rows;
    const int m0 = mtile * TILE_M;
    const int n0 = ntile * TILE_N;

    // ---- producer bases: 8 x 16B per thread per stage ----
    const int pr = tid >> 3;          // 0..31
    const int pj = tid & 7;           // 16B segment within 128B row
    const __half* gA0 = g_Xh + (size_t)(m0 + pr) * K_TOTAL + pj * 8;
    const __half* gB0 = g_Wh + (size_t)(n0 + pr) * K_TOTAL + pj * 8;
    const uint32_t swzA = SWZ((uint32_t)(pr * 128 + pj * 16));
    const uint32_t swzB = (uint32_t)A_TILE_BYTES + SWZ((uint32_t)(pr * 128 + pj * 16));

    // first half: A rows (4 x 16B); second half: B rows (4 x 16B) + commit
    auto produce_a = [&](int c, int slot) {
        uint32_t dstb = sb + (uint32_t)slot * STAGE_BYTES;
        const __half* ga = gA0 + (size_t)c * TILE_K;
#pragma unroll
        for (int i = 0; i < 4; ++i)
            cp_async16(dstb + swzA + i * 4096u, ga + (size_t)i * 32 * K_TOTAL);
    };
    auto produce_b = [&](int c, int slot) {
        uint32_t dstb = sb + (uint32_t)slot * STAGE_BYTES;
        const __half* gb = gB0 + (size_t)c * TILE_K;
#pragma unroll
        for (int i = 0; i < 4; ++i)
            cp_async16(dstb + swzB + i * 4096u, gb + (size_t)i * 32 * K_TOTAL);
        cp_commit();
    };

    // ---- prologue: stages 0..S-2 in flight ----
#pragma unroll
    for (int c = 0; c < STAGES - 1; ++c) { produce_a(c, c); produce_b(c, c); }
    cp_wait<STAGES - 2>();
    __syncthreads();

    // ---- accumulators: 8 warps (2x4), warp tile 64x32 ----
    float acc[4][4][4];
#pragma unroll
    for (int mt = 0; mt < 4; ++mt)
#pragma unroll
        for (int nt = 0; nt < 4; ++nt)
#pragma unroll
            for (int jj = 0; jj < 4; ++jj) acc[mt][nt][jj] = 0.0f;

    const int wm = wid & 1, wn = wid >> 1;
    const int mbase = wm * 64, nbase = wn * 32;
    const int qr = lid >> 2, qc = lid & 3;

    // ---- ldmatrix per-thread address offsets (swizzle folded to XOR const) ----
    uint32_t aoff[4];
    {
        int rowl = lid & 15;
        uint32_t kadd = (uint32_t)(lid >> 4) * 16u;
#pragma unroll
        for (int mt = 0; mt < 4; ++mt) {
            int row = mbase + mt * 16 + rowl;
            uint32_t cb = kadd ^ (uint32_t)((row & 7) * 16);
            aoff[mt] = (uint32_t)(row * 128) + cb;
        }
    }
    uint32_t boff[2];
    {
        int rowl = (lid & 7) + ((lid >> 4) << 3);
        uint32_t kadd = (uint32_t)((lid >> 3) & 1) * 16u;
#pragma unroll
        for (int p = 0; p < 2; ++p) {
            int row = nbase + p * 16 + rowl;
            uint32_t cb = kadd ^ (uint32_t)((row & 7) * 16);
            boff[p] = (uint32_t)A_TILE_BYTES + (uint32_t)(row * 128) + cb;
        }
    }

    int slot_cons = 0;                 // c % 3
    int slot_prod = STAGES - 1;        // (c + S-1) % 3
#pragma unroll 1
    for (int c = 0; c < KCHUNKS; ++c) {
        const bool do_prod = (c + STAGES - 1 < KCHUNKS);
        const uint32_t stb = sb + (uint32_t)slot_cons * STAGE_BYTES;

#pragma unroll
        for (int kk = 0; kk < 4; ++kk) {          // 4 x k16 within 64-K chunk
            const uint32_t kx = (uint32_t)kk * 32u;  // bits 5-6; XOR-composable
            uint32_t a[4][4], b[2][4];
            // B first (2 ops) then A (4 ops): shortest path to first HMMA
#pragma unroll
            for (int p = 0; p < 2; ++p)
                ldsm_x4(b[p][0], b[p][1], b[p][2], b[p][3],
                        stb + (boff[p] ^ kx));
#pragma unroll
            for (int mt = 0; mt < 4; ++mt)
                ldsm_x4(a[mt][0], a[mt][1], a[mt][2], a[mt][3],
                        stb + (aoff[mt] ^ kx));
#pragma unroll
            for (int mt = 0; mt < 4; ++mt)
#pragma unroll
                for (int p = 0; p < 2; ++p) {
                    mma_f16(acc[mt][2 * p],     a[mt], &b[p][0]);
                    mma_f16(acc[mt][2 * p + 1], a[mt], &b[p][2]);
                }
            // spread producer bursts across the whole chunk, away from the
            // post-barrier LDSM spike and from each other
            if (kk == 0 && do_prod) produce_a(c + STAGES - 1, slot_prod);
            if (kk == 2 && do_prod) produce_b(c + STAGES - 1, slot_prod);
        }

        cp_wait<STAGES - 2>();
        __syncthreads();
        if (++slot_cons == STAGES) slot_cons = 0;
        if (++slot_prod == STAGES) slot_prod = 0;
    }

    // ---- epilogue: regs -> GMEM with q/k/v region remap ----
    // out column n -> region r = n>>12, elem e = n&4095; region stride M*4096
    {
        const int rgn = n0 >> 12;
        float* obase = out + (size_t)rgn * ((size_t)M_TOTAL * 4096)
                           + (size_t)m0 * 4096 + (size_t)(n0 & 4095);
#pragma unroll
        for (int mt = 0; mt < 4; ++mt) {
            int m = mbase + mt * 16 + qr;
#pragma unroll
            for (int nt = 0; nt < 4; ++nt) {
                int ncol = nbase + nt * 8 + 2 * qc;
                stg_cs_v2(obase + (size_t)m * 4096 + ncol,
                          acc[mt][nt][0], acc[mt][nt][1]);
                stg_cs_v2(obase + (size_t)(m + 8) * 4096 + ncol,
                          acc[mt][nt][2], acc[mt][nt][3]);
            }
        }
    }
}

// ================= launch =================
extern "C" void kernel_launch(void* const* d_in, const int* in_sizes, int n_in,
                              void* d_out, int out_size) {
    const float* X = (const float*)d_in[0];   // hidden_states [4,4096,4096]
    const float* W = (const float*)d_in[1];   // qkv_proj [12288,4096]
    float* out = (float*)d_out;               // q|k|v, 3 x [16384,4096]
    (void)in_sizes; (void)n_in; (void)out_size;

    cudaFuncSetAttribute(qkv_gemm_kernel,
                         cudaFuncAttributeMaxDynamicSharedMemorySize, SMEM_BYTES);

    cvt_both_kernel<<<2368, 256>>>(X, W);
    qkv_gemm_kernel<<<MT * NT, 256, SMEM_BYTES>>>(out);
}

// round 14
// speedup vs baseline: 1.5153x; 1.5153x over previous
#include <cuda_runtime.h>
#include <cuda_fp16.h>
#include <cstdint>

// ================= problem dims =================
static constexpr int M_TOTAL = 16384;   // B*S = 4*4096
static constexpr int N_TOTAL = 12288;   // 3*E
static constexpr int K_TOTAL = 4096;    // E
static constexpr int TILE_M  = 128;
static constexpr int TILE_N  = 128;
static constexpr int TILE_K  = 64;      // 64 halves = 128B rows (swizzle atom)
static constexpr int STAGES  = 3;
static constexpr int KCHUNKS = K_TOTAL / TILE_K;  // 64
static constexpr int MT = M_TOTAL / TILE_M;       // 128
static constexpr int NT = N_TOTAL / TILE_N;       // 96
static constexpr int GROUP_M = 32;

static constexpr int A_TILE_BYTES = TILE_M * TILE_K * 2;   // 16384
static constexpr int B_TILE_BYTES = TILE_N * TILE_K * 2;   // 16384
static constexpr int STAGE_BYTES  = A_TILE_BYTES + B_TILE_BYTES; // 32768
static constexpr int SMEM_BYTES   = STAGES * STAGE_BYTES;        // 98304

// fp16 copies of the inputs (RN). fp16 mantissa == tf32 mantissa (10 bits).
__device__ __half g_Xh[(size_t)M_TOTAL * K_TOTAL];
__device__ __half g_Wh[(size_t)N_TOTAL * K_TOTAL];

// ================= helpers =================
__device__ __forceinline__ uint32_t smem_u32(const void* p) {
    uint32_t a;
    asm("{ .reg .u64 t; cvta.to.shared.u64 t, %1; cvt.u32.u64 %0, t; }"
        : "=r"(a) : "l"(p));
    return a;
}

__device__ __forceinline__ void cp_async16(uint32_t dst, const void* src) {
    asm volatile("cp.async.cg.shared.global [%0], [%1], 16;" :: "r"(dst), "l"(src));
}
__device__ __forceinline__ void cp_commit() {
    asm volatile("cp.async.commit_group;" ::: "memory");
}
template <int N>
__device__ __forceinline__ void cp_wait() {
    asm volatile("cp.async.wait_group %0;" :: "n"(N) : "memory");
}

// 128B-block swizzle: XOR 16B-unit index with low 3 row bits
#define SWZ(o) ((o) ^ (((o) >> 3) & 0x70))

// ldmatrix x4: four 8x8 b16 matrices, per-lane row addresses
__device__ __forceinline__ void ldsm_x4(uint32_t& r0, uint32_t& r1,
                                        uint32_t& r2, uint32_t& r3,
                                        uint32_t addr) {
    asm volatile("ldmatrix.sync.aligned.m8n8.x4.shared.b16 {%0,%1,%2,%3}, [%4];"
                 : "=r"(r0), "=r"(r1), "=r"(r2), "=r"(r3) : "r"(addr));
}

// fp16 MMA, fp32 accumulate (sm_80+, legal on plain sm_103 target)
__device__ __forceinline__ void mma_f16(float* c, const uint32_t* a,
                                        const uint32_t* b) {
    asm volatile(
        "mma.sync.aligned.m16n8k16.row.col.f32.f16.f16.f32 "
        "{%0,%1,%2,%3}, {%4,%5,%6,%7}, {%8,%9}, {%0,%1,%2,%3};"
        : "+f"(c[0]), "+f"(c[1]), "+f"(c[2]), "+f"(c[3])
        : "r"(a[0]), "r"(a[1]), "r"(a[2]), "r"(a[3]),
          "r"(b[0]), "r"(b[1]));
}

// streaming 8B store (output is write-once, never re-read by this grid)
__device__ __forceinline__ void stg_cs_v2(float* p, float x, float y) {
    asm volatile("st.global.cs.v2.f32 [%0], {%1, %2};"
                 :: "l"(p), "f"(x), "f"(y) : "memory");
}

// ================= fp32 -> fp16 RN pre-pass (both arrays, one launch) =======
static constexpr int NX4 = M_TOTAL * (K_TOTAL / 4);   // X float4 count
static constexpr int NW4 = N_TOTAL * (K_TOTAL / 4);   // W float4 count

__global__ void __launch_bounds__(256)
cvt_both_kernel(const float* __restrict__ X, const float* __restrict__ W) {
    int i = blockIdx.x * blockDim.x + threadIdx.x;
    int stride = gridDim.x * blockDim.x;
    for (; i < NX4 + NW4; i += stride) {
        const float4* s;
        __half* dst;
        int k;
        if (i < NX4) { s = (const float4*)X; dst = g_Xh; k = i; }
        else         { s = (const float4*)W; dst = g_Wh; k = i - NX4; }
        float4 v = s[k];
        __half2 h0 = __floats2half2_rn(v.x, v.y);
        __half2 h1 = __floats2half2_rn(v.z, v.w);
        uint2 pack = make_uint2(*(uint32_t*)&h0, *(uint32_t*)&h1);
        *(uint2*)(dst + (size_t)k * 4) = pack;
    }
}

// ================= GEMM kernel =================
__global__ void __launch_bounds__(256, 2)
qkv_gemm_kernel(float* __restrict__ out) {
    extern __shared__ __align__(1024) char smem[];
    const uint32_t sb = smem_u32(smem);
    const int tid = threadIdx.x;
    const int wid = tid >> 5;
    const int lid = tid & 31;

    // ---- tile mapping (grouped raster for L2 reuse) ----
    int bid = blockIdx.x;
    const int TPG = GROUP_M * NT;
    int g   = bid / TPG;
    int rem = bid % TPG;
    int m0g = g * GROUP_M;
    int rows = (MT - m0g) < GROUP_M ? (MT - m0g) : GROUP_M;
    int mtile = m0g + rem % rows;
    int ntile = rem / rows;
    const int m0 = mtile * TILE_M;
    const int n0 = ntile * TILE_N;

    // ---- producer bases: 8 x 16B per thread per stage ----
    const int pr = tid >> 3;          // 0..31
    const int pj = tid & 7;           // 16B segment within 128B row
    const __half* gA0 = g_Xh + (size_t)(m0 + pr) * K_TOTAL + pj * 8;
    const __half* gB0 = g_Wh + (size_t)(n0 + pr) * K_TOTAL + pj * 8;
    const uint32_t swzA = SWZ((uint32_t)(pr * 128 + pj * 16));
    const uint32_t swzB = (uint32_t)A_TILE_BYTES + SWZ((uint32_t)(pr * 128 + pj * 16));

    // first half: A rows (4 x 16B); second half: B rows (4 x 16B) + commit
    auto produce_a = [&](int c, int slot) {
        uint32_t dstb = sb + (uint32_t)slot * STAGE_BYTES;
        const __half* ga = gA0 + (size_t)c * TILE_K;
#pragma unroll
        for (int i = 0; i < 4; ++i)
            cp_async16(dstb + swzA + i * 4096u, ga + (size_t)i * 32 * K_TOTAL);
    };
    auto produce_b = [&](int c, int slot) {
        uint32_t dstb = sb + (uint32_t)slot * STAGE_BYTES;
        const __half* gb = gB0 + (size_t)c * TILE_K;
#pragma unroll
        for (int i = 0; i < 4; ++i)
            cp_async16(dstb + swzB + i * 4096u, gb + (size_t)i * 32 * K_TOTAL);
        cp_commit();
    };

    // ---- prologue: stages 0..S-2 in flight ----
#pragma unroll
    for (int c = 0; c < STAGES - 1; ++c) { produce_a(c, c); produce_b(c, c); }
    cp_wait<STAGES - 2>();
    __syncthreads();

    // ---- accumulators: 8 warps (2x4), warp tile 64x32 ----
    float acc[4][4][4];
#pragma unroll
    for (int mt = 0; mt < 4; ++mt)
#pragma unroll
        for (int nt = 0; nt < 4; ++nt)
#pragma unroll
            for (int jj = 0; jj < 4; ++jj) acc[mt][nt][jj] = 0.0f;

    const int wm = wid & 1, wn = wid >> 1;
    const int mbase = wm * 64, nbase = wn * 32;
    const int qr = lid >> 2, qc = lid & 3;

    // ---- ldmatrix per-thread address offsets (swizzle folded to XOR const) ----
    uint32_t aoff[4];
    {
        int rowl = lid & 15;
        uint32_t kadd = (uint32_t)(lid >> 4) * 16u;
#pragma unroll
        for (int mt = 0; mt < 4; ++mt) {
            int row = mbase + mt * 16 + rowl;
            uint32_t cb = kadd ^ (uint32_t)((row & 7) * 16);
            aoff[mt] = (uint32_t)(row * 128) + cb;
        }
    }
    uint32_t boff[2];
    {
        int rowl = (lid & 7) + ((lid >> 4) << 3);
        uint32_t kadd = (uint32_t)((lid >> 3) & 1) * 16u;
#pragma unroll
        for (int p = 0; p < 2; ++p) {
            int row = nbase + p * 16 + rowl;
            uint32_t cb = kadd ^ (uint32_t)((row & 7) * 16);
            boff[p] = (uint32_t)A_TILE_BYTES + (uint32_t)(row * 128) + cb;
        }
    }

    int slot_cons = 0;                 // c % 3
    int slot_prod = STAGES - 1;        // (c + S-1) % 3
#pragma unroll 1
    for (int c = 0; c < KCHUNKS; ++c) {
        const bool do_prod = (c + STAGES - 1 < KCHUNKS);
        const uint32_t stb = sb + (uint32_t)slot_cons * STAGE_BYTES;

#pragma unroll
        for (int kk = 0; kk < 4; ++kk) {          // 4 x k16 within 64-K chunk
            const uint32_t kx = (uint32_t)kk * 32u;  // bits 5-6; XOR-composable
            uint32_t a[4][4], b[2][4];
            // B first (2 ops) then A (4 ops): shortest path to first HMMA
#pragma unroll
            for (int p = 0; p < 2; ++p)
                ldsm_x4(b[p][0], b[p][1], b[p][2], b[p][3],
                        stb + (boff[p] ^ kx));
#pragma unroll
            for (int mt = 0; mt < 4; ++mt)
                ldsm_x4(a[mt][0], a[mt][1], a[mt][2], a[mt][3],
                        stb + (aoff[mt] ^ kx));
#pragma unroll
            for (int mt = 0; mt < 4; ++mt)
#pragma unroll
                for (int p = 0; p < 2; ++p) {
                    mma_f16(acc[mt][2 * p],     a[mt], &b[p][0]);
                    mma_f16(acc[mt][2 * p + 1], a[mt], &b[p][2]);
                }
            // spread the producer bursts away from the post-barrier LDSM spike;
            // commit at kk=1 keeps ~3 MMA bundles of commit-to-wait lead time
            // (kk=2 regressed 51% in R11 — do not delay the commit further)
            if (kk == 0 && do_prod) produce_a(c + STAGES - 1, slot_prod);
            if (kk == 1 && do_prod) produce_b(c + STAGES - 1, slot_prod);
        }

        cp_wait<STAGES - 2>();
        __syncthreads();
        if (++slot_cons == STAGES) slot_cons = 0;
        if (++slot_prod == STAGES) slot_prod = 0;
    }

    // ---- epilogue: regs -> GMEM with q/k/v region remap ----
    // out column n -> region r = n>>12, elem e = n&4095; region stride M*4096
    {
        const int rgn = n0 >> 12;
        float* obase = out + (size_t)rgn * ((size_t)M_TOTAL * 4096)
                           + (size_t)m0 * 4096 + (size_t)(n0 & 4095);
#pragma unroll
        for (int mt = 0; mt < 4; ++mt) {
            int m = mbase + mt * 16 + qr;
#pragma unroll
            for (int nt = 0; nt < 4; ++nt) {
                int ncol = nbase + nt * 8 + 2 * qc;
                stg_cs_v2(obase + (size_t)m * 4096 + ncol,
                          acc[mt][nt][0], acc[mt][nt][1]);
                stg_cs_v2(obase + (size_t)(m + 8) * 4096 + ncol,
                          acc[mt][nt][2], acc[mt][nt][3]);
            }
        }
    }
}

// ================= launch =================
extern "C" void kernel_launch(void* const* d_in, const int* in_sizes, int n_in,
                              void* d_out, int out_size) {
    const float* X = (const float*)d_in[0];   // hidden_states [4,4096,4096]
    const float* W = (const float*)d_in[1];   // qkv_proj [12288,4096]
    float* out = (float*)d_out;               // q|k|v, 3 x [16384,4096]
    (void)in_sizes; (void)n_in; (void)out_size;

    cudaFuncSetAttribute(qkv_gemm_kernel,
                         cudaFuncAttributeMaxDynamicSharedMemorySize, SMEM_BYTES);

    cvt_both_kernel<<<2368, 256>>>(X, W);
    qkv_gemm_kernel<<<MT * NT, 256, SMEM_BYTES>>>(out);
}

// round 15
// speedup vs baseline: 1.5579x; 1.0281x over previous
#include <cuda_runtime.h>
#include <cuda_fp16.h>
#include <cstdint>

// ================= problem dims =================
static constexpr int M_TOTAL = 16384;   // B*S = 4*4096
static constexpr int N_TOTAL = 12288;   // 3*E
static constexpr int K_TOTAL = 4096;    // E
static constexpr int TILE_M  = 128;
static constexpr int TILE_N  = 128;
static constexpr int TILE_K  = 64;      // 64 halves = 128B rows (swizzle atom)
static constexpr int STAGES  = 3;
static constexpr int KCHUNKS = K_TOTAL / TILE_K;  // 64
static constexpr int MT = M_TOTAL / TILE_M;       // 128
static constexpr int NT = N_TOTAL / TILE_N;       // 96
static constexpr int GROUP_M = 32;

static constexpr int A_TILE_BYTES = TILE_M * TILE_K * 2;   // 16384
static constexpr int B_TILE_BYTES = TILE_N * TILE_K * 2;   // 16384
static constexpr int STAGE_BYTES  = A_TILE_BYTES + B_TILE_BYTES; // 32768
static constexpr int SMEM_HDR    = 1024;   // mbarriers live here
static constexpr int SMEM_BYTES  = SMEM_HDR + STAGES * STAGE_BYTES; // 99328

// header offsets
static constexpr uint32_t OFF_FULL  = 0;    // 3 x 8B
static constexpr uint32_t OFF_EMPTY = 32;   // 3 x 8B

// fp16 copies of the inputs (RN). fp16 mantissa == tf32 mantissa (10 bits).
__device__ __half g_Xh[(size_t)M_TOTAL * K_TOTAL];
__device__ __half g_Wh[(size_t)N_TOTAL * K_TOTAL];

// ================= helpers =================
__device__ __forceinline__ uint32_t smem_u32(const void* p) {
    uint32_t a;
    asm("{ .reg .u64 t; cvta.to.shared.u64 t, %1; cvt.u32.u64 %0, t; }"
        : "=r"(a) : "l"(p));
    return a;
}

__device__ __forceinline__ void cp_async16(uint32_t dst, const void* src) {
    asm volatile("cp.async.cg.shared.global [%0], [%1], 16;" :: "r"(dst), "l"(src));
}

__device__ __forceinline__ void mbar_init(uint32_t a, uint32_t cnt) {
    asm volatile("mbarrier.init.shared.b64 [%0], %1;" :: "r"(a), "r"(cnt) : "memory");
}
__device__ __forceinline__ void mbar_arrive(uint32_t a) {
    asm volatile("mbarrier.arrive.shared.b64 _, [%0];" :: "r"(a) : "memory");
}
// arrive fires when ALL prior cp.async of this thread have completed;
// .noinc: the async arrive counts toward the init count (R2 bug was missing this)
__device__ __forceinline__ void cpasync_arrive_noinc(uint32_t a) {
    asm volatile("cp.async.mbarrier.arrive.noinc.shared.b64 [%0];" :: "r"(a) : "memory");
}
__device__ __forceinline__ void mbar_wait(uint32_t a, uint32_t parity) {
    uint32_t done;
    asm volatile("{\n\t.reg .pred p;\n\t"
                 "mbarrier.try_wait.parity.acquire.cta.shared::cta.b64 p, [%1], %2;\n\t"
                 "selp.b32 %0, 1, 0, p;\n\t}"
                 : "=r"(done) : "r"(a), "r"(parity) : "memory");
    if (!done) {
        asm volatile("{\n\t.reg .pred P1;\n\t"
                     "WL_%=:\n\t"
                     "mbarrier.try_wait.parity.acquire.cta.shared::cta.b64 P1, [%0], %1, 0x989680;\n\t"
                     "@P1 bra.uni WD_%=;\n\t"
                     "bra.uni WL_%=;\n\t"
                     "WD_%=:\n\t}"
                     :: "r"(a), "r"(parity) : "memory");
    }
}

// 128B-block swizzle: XOR 16B-unit index with low 3 row bits
#define SWZ(o) ((o) ^ (((o) >> 3) & 0x70))

// ldmatrix x4: four 8x8 b16 matrices, per-lane row addresses
__device__ __forceinline__ void ldsm_x4(uint32_t& r0, uint32_t& r1,
                                        uint32_t& r2, uint32_t& r3,
                                        uint32_t addr) {
    asm volatile("ldmatrix.sync.aligned.m8n8.x4.shared.b16 {%0,%1,%2,%3}, [%4];"
                 : "=r"(r0), "=r"(r1), "=r"(r2), "=r"(r3) : "r"(addr));
}

// fp16 MMA, fp32 accumulate (sm_80+, legal on plain sm_103 target)
__device__ __forceinline__ void mma_f16(float* c, const uint32_t* a,
                                        const uint32_t* b) {
    asm volatile(
        "mma.sync.aligned.m16n8k16.row.col.f32.f16.f16.f32 "
        "{%0,%1,%2,%3}, {%4,%5,%6,%7}, {%8,%9}, {%0,%1,%2,%3};"
        : "+f"(c[0]), "+f"(c[1]), "+f"(c[2]), "+f"(c[3])
        : "r"(a[0]), "r"(a[1]), "r"(a[2]), "r"(a[3]),
          "r"(b[0]), "r"(b[1]));
}

// streaming 8B store (output is write-once, never re-read by this grid)
__device__ __forceinline__ void stg_cs_v2(float* p, float x, float y) {
    asm volatile("st.global.cs.v2.f32 [%0], {%1, %2};"
                 :: "l"(p), "f"(x), "f"(y) : "memory");
}

// ================= fp32 -> fp16 RN pre-pass (both arrays, one launch) =======
static constexpr int NX4 = M_TOTAL * (K_TOTAL / 4);   // X float4 count
static constexpr int NW4 = N_TOTAL * (K_TOTAL / 4);   // W float4 count

__global__ void __launch_bounds__(256)
cvt_both_kernel(const float* __restrict__ X, const float* __restrict__ W) {
    int i = blockIdx.x * blockDim.x + threadIdx.x;
    int stride = gridDim.x * blockDim.x;
    for (; i < NX4 + NW4; i += stride) {
        const float4* s;
        __half* dst;
        int k;
        if (i < NX4) { s = (const float4*)X; dst = g_Xh; k = i; }
        else         { s = (const float4*)W; dst = g_Wh; k = i - NX4; }
        float4 v = s[k];
        __half2 h0 = __floats2half2_rn(v.x, v.y);
        __half2 h1 = __floats2half2_rn(v.z, v.w);
        uint2 pack = make_uint2(*(uint32_t*)&h0, *(uint32_t*)&h1);
        *(uint2*)(dst + (size_t)k * 4) = pack;
    }
}

// ================= GEMM kernel =================
__global__ void __launch_bounds__(256, 2)
qkv_gemm_kernel(float* __restrict__ out) {
    extern __shared__ __align__(1024) char smem[];
    const uint32_t sb = smem_u32(smem);
    const int tid = threadIdx.x;
    const int wid = tid >> 5;
    const int lid = tid & 31;

    // ---- tile mapping (grouped raster for L2 reuse) ----
    int bid = blockIdx.x;
    const int TPG = GROUP_M * NT;
    int g   = bid / TPG;
    int rem = bid % TPG;
    int m0g = g * GROUP_M;
    int rows = (MT - m0g) < GROUP_M ? (MT - m0g) : GROUP_M;
    int mtile = m0g + rem % rows;
    int ntile = rem / rows;
    const int m0 = mtile * TILE_M;
    const int n0 = ntile * TILE_N;

    // ---- mbarrier init: full[s] count=256 (async arrives), empty[s] count=8 ----
    const uint32_t FULLB  = sb + OFF_FULL;
    const uint32_t EMPTYB = sb + OFF_EMPTY;
    if (tid == 0) {
#pragma unroll
        for (int s = 0; s < STAGES; ++s) {
            mbar_init(FULLB  + 8u * s, 256);
            mbar_init(EMPTYB + 8u * s, 8);
        }
    }
    __syncthreads();   // only CTA-wide barrier: publish barrier init

    // ---- producer bases: 8 x 16B per thread per stage ----
    const int pr = tid >> 3;          // 0..31
    const int pj = tid & 7;           // 16B segment within 128B row
    const __half* gA0 = g_Xh + (size_t)(m0 + pr) * K_TOTAL + pj * 8;
    const __half* gB0 = g_Wh + (size_t)(n0 + pr) * K_TOTAL + pj * 8;
    const uint32_t swzA = SWZ((uint32_t)(pr * 128 + pj * 16));
    const uint32_t swzB = (uint32_t)A_TILE_BYTES + SWZ((uint32_t)(pr * 128 + pj * 16));

    auto produce_a = [&](int c, int slot) {
        uint32_t dstb = sb + SMEM_HDR + (uint32_t)slot * STAGE_BYTES;
        const __half* ga = gA0 + (size_t)c * TILE_K;
#pragma unroll
        for (int i = 0; i < 4; ++i)
            cp_async16(dstb + swzA + i * 4096u, ga + (size_t)i * 32 * K_TOTAL);
    };
    auto produce_b = [&](int c, int slot) {
        uint32_t dstb = sb + SMEM_HDR + (uint32_t)slot * STAGE_BYTES;
        const __half* gb = gB0 + (size_t)c * TILE_K;
#pragma unroll
        for (int i = 0; i < 4; ++i)
            cp_async16(dstb + swzB + i * 4096u, gb + (size_t)i * 32 * K_TOTAL);
    };

    // ---- prologue: produce chunks 0,1 (fresh empty barriers: no wait needed) ----
    produce_a(0, 0); produce_b(0, 0); cpasync_arrive_noinc(FULLB + 0);
    produce_a(1, 1); produce_b(1, 1); cpasync_arrive_noinc(FULLB + 8);

    // ---- accumulators: 8 warps (2x4), warp tile 64x32 ----
    float acc[4][4][4];
#pragma unroll
    for (int mt = 0; mt < 4; ++mt)
#pragma unroll
        for (int nt = 0; nt < 4; ++nt)
#pragma unroll
            for (int jj = 0; jj < 4; ++jj) acc[mt][nt][jj] = 0.0f;

    const int wm = wid & 1, wn = wid >> 1;
    const int mbase = wm * 64, nbase = wn * 32;
    const int qr = lid >> 2, qc = lid & 3;

    // ---- ldmatrix per-thread address offsets (swizzle folded to XOR const) ----
    uint32_t aoff[4];
    {
        int rowl = lid & 15;
        uint32_t kadd = (uint32_t)(lid >> 4) * 16u;
#pragma unroll
        for (int mt = 0; mt < 4; ++mt) {
            int row = mbase + mt * 16 + rowl;
            uint32_t cb = kadd ^ (uint32_t)((row & 7) * 16);
            aoff[mt] = (uint32_t)(row * 128) + cb;
        }
    }
    uint32_t boff[2];
    {
        int rowl = (lid & 7) + ((lid >> 4) << 3);
        uint32_t kadd = (uint32_t)((lid >> 3) & 1) * 16u;
#pragma unroll
        for (int p = 0; p < 2; ++p) {
            int row = nbase + p * 16 + rowl;
            uint32_t cb = kadd ^ (uint32_t)((row & 7) * 16);
            boff[p] = (uint32_t)A_TILE_BYTES + (uint32_t)(row * 128) + cb;
        }
    }

    // consumer cursor: slot = c%3, cph = (c/3)&1
    int slot = 0, cph = 0;
#pragma unroll 1
    for (int c = 0; c < KCHUNKS; ++c) {
        const bool do_prod = (c + 2 < KCHUNKS);
        // producer slot/phase derived from consumer cursor:
        // pc=c+2: pslot=(slot+2)%3; k_p=(pc/3): pph = (slot==0) ? cph : cph^1
        const int pslot = (slot == 0) ? 2 : slot - 1;
        const int pph   = (slot == 0) ? cph : (cph ^ 1);

        // wait chunk-c data: full[slot] phase (c/3) complete
        mbar_wait(FULLB + 8u * slot, (uint32_t)cph);

        const uint32_t stb = sb + SMEM_HDR + (uint32_t)slot * STAGE_BYTES;

#pragma unroll
        for (int kk = 0; kk < 4; ++kk) {          // 4 x k16 within 64-K chunk
            const uint32_t kx = (uint32_t)kk * 32u;  // bits 5-6; XOR-composable
            uint32_t a[4][4], b[2][4];
            // B first (2 ops) then A (4 ops): shortest path to first HMMA
#pragma unroll
            for (int p = 0; p < 2; ++p)
                ldsm_x4(b[p][0], b[p][1], b[p][2], b[p][3],
                        stb + (boff[p] ^ kx));
#pragma unroll
            for (int mt = 0; mt < 4; ++mt)
                ldsm_x4(a[mt][0], a[mt][1], a[mt][2], a[mt][3],
                        stb + (aoff[mt] ^ kx));
#pragma unroll
            for (int mt = 0; mt < 4; ++mt)
#pragma unroll
                for (int p = 0; p < 2; ++p) {
                    mma_f16(acc[mt][2 * p],     a[mt], &b[p][0]);
                    mma_f16(acc[mt][2 * p + 1], a[mt], &b[p][2]);
                }
            // producer spread (R10 winner shape; R11: do NOT delay past kk=1):
            // empty-wait parity = pph^1 ("phase k_p-1 completed")
            if (kk == 0 && do_prod) {
                mbar_wait(EMPTYB + 8u * pslot, (uint32_t)(pph ^ 1));
                produce_a(c + 2, pslot);
            }
            if (kk == 1 && do_prod) {
                produce_b(c + 2, pslot);
                cpasync_arrive_noinc(FULLB + 8u * pslot);
            }
        }

        // release slot: all 32 lanes' LDSM reads done (warp-synchronous MMA
        // consumed them); fence with syncwarp, lane 0 arrives (count=8)
        __syncwarp();
        if (lid == 0) mbar_arrive(EMPTYB + 8u * slot);

        if (++slot == STAGES) { slot = 0; cph ^= 1; }
    }

    // ---- epilogue: regs -> GMEM with q/k/v region remap ----
    // out column n -> region r = n>>12, elem e = n&4095; region stride M*4096
    {
        const int rgn = n0 >> 12;
        float* obase = out + (size_t)rgn * ((size_t)M_TOTAL * 4096)
                           + (size_t)m0 * 4096 + (size_t)(n0 & 4095);
#pragma unroll
        for (int mt = 0; mt < 4; ++mt) {
            int m = mbase + mt * 16 + qr;
#pragma unroll
            for (int nt = 0; nt < 4; ++nt) {
                int ncol = nbase + nt * 8 + 2 * qc;
                stg_cs_v2(obase + (size_t)m * 4096 + ncol,
                          acc[mt][nt][0], acc[mt][nt][1]);
                stg_cs_v2(obase + (size_t)(m + 8) * 4096 + ncol,
                          acc[mt][nt][2], acc[mt][nt][3]);
            }
        }
    }
}

// ================= launch =================
extern "C" void kernel_launch(void* const* d_in, const int* in_sizes, int n_in,
                              void* d_out, int out_size) {
    const float* X = (const float*)d_in[0];   // hidden_states [4,4096,4096]
    const float* W = (const float*)d_in[1];   // qkv_proj [12288,4096]
    float* out = (float*)d_out;               // q|k|v, 3 x [16384,4096]
    (void)in_sizes; (void)n_in; (void)out_size;

    cudaFuncSetAttribute(qkv_gemm_kernel,
                         cudaFuncAttributeMaxDynamicSharedMemorySize, SMEM_BYTES);

    cvt_both_kernel<<<2368, 256>>>(X, W);
    qkv_gemm_kernel<<<MT * NT, 256, SMEM_BYTES>>>(out);
}

// round 16
// speedup vs baseline: 1.5765x; 1.0119x over previous
#include <cuda_runtime.h>
#include <cuda_fp16.h>
#include <cstdint>

// ================= problem dims =================
static constexpr int M_TOTAL = 16384;   // B*S = 4*4096
static constexpr int N_TOTAL = 12288;   // 3*E
static constexpr int K_TOTAL = 4096;    // E
static constexpr int TILE_M  = 128;
static constexpr int TILE_N  = 128;
static constexpr int TILE_K  = 64;      // 64 halves = 128B rows (swizzle atom)
static constexpr int STAGES  = 3;
static constexpr int KCHUNKS = K_TOTAL / TILE_K;  // 64
static constexpr int MT = M_TOTAL / TILE_M;       // 128
static constexpr int NT = N_TOTAL / TILE_N;       // 96
static constexpr int GROUP_M = 32;

static constexpr int A_TILE_BYTES = TILE_M * TILE_K * 2;   // 16384
static constexpr int B_TILE_BYTES = TILE_N * TILE_K * 2;   // 16384
static constexpr int STAGE_BYTES  = A_TILE_BYTES + B_TILE_BYTES; // 32768
static constexpr int SMEM_HDR    = 1024;   // mbarriers live here
static constexpr int SMEM_BYTES  = SMEM_HDR + STAGES * STAGE_BYTES; // 99328

// header offsets
static constexpr uint32_t OFF_FULL  = 0;    // 3 x 8B
static constexpr uint32_t OFF_EMPTY = 32;   // 3 x 8B

// fp16 copies of the inputs (RN). fp16 mantissa == tf32 mantissa (10 bits).
__device__ __half g_Xh[(size_t)M_TOTAL * K_TOTAL];
__device__ __half g_Wh[(size_t)N_TOTAL * K_TOTAL];

// ================= helpers =================
__device__ __forceinline__ uint32_t smem_u32(const void* p) {
    uint32_t a;
    asm("{ .reg .u64 t; cvta.to.shared.u64 t, %1; cvt.u32.u64 %0, t; }"
        : "=r"(a) : "l"(p));
    return a;
}

__device__ __forceinline__ void cp_async16(uint32_t dst, const void* src) {
    asm volatile("cp.async.cg.shared.global [%0], [%1], 16;" :: "r"(dst), "l"(src));
}

__device__ __forceinline__ void mbar_init(uint32_t a, uint32_t cnt) {
    asm volatile("mbarrier.init.shared.b64 [%0], %1;" :: "r"(a), "r"(cnt) : "memory");
}
__device__ __forceinline__ void mbar_arrive(uint32_t a) {
    asm volatile("mbarrier.arrive.shared.b64 _, [%0];" :: "r"(a) : "memory");
}
// arrive fires when ALL prior cp.async of this thread have completed;
// .noinc: the async arrive counts toward the init count
__device__ __forceinline__ void cpasync_arrive_noinc(uint32_t a) {
    asm volatile("cp.async.mbarrier.arrive.noinc.shared.b64 [%0];" :: "r"(a) : "memory");
}
__device__ __forceinline__ void mbar_wait(uint32_t a, uint32_t parity) {
    uint32_t done;
    asm volatile("{\n\t.reg .pred p;\n\t"
                 "mbarrier.try_wait.parity.acquire.cta.shared::cta.b64 p, [%1], %2;\n\t"
                 "selp.b32 %0, 1, 0, p;\n\t}"
                 : "=r"(done) : "r"(a), "r"(parity) : "memory");
    if (!done) {
        asm volatile("{\n\t.reg .pred P1;\n\t"
                     "WL_%=:\n\t"
                     "mbarrier.try_wait.parity.acquire.cta.shared::cta.b64 P1, [%0], %1, 0x989680;\n\t"
                     "@P1 bra.uni WD_%=;\n\t"
                     "bra.uni WL_%=;\n\t"
                     "WD_%=:\n\t}"
                     :: "r"(a), "r"(parity) : "memory");
    }
}

// 128B-block swizzle: XOR 16B-unit index with low 3 row bits
#define SWZ(o) ((o) ^ (((o) >> 3) & 0x70))

// ldmatrix x4: four 8x8 b16 matrices, per-lane row addresses
__device__ __forceinline__ void ldsm_x4(uint32_t& r0, uint32_t& r1,
                                        uint32_t& r2, uint32_t& r3,
                                        uint32_t addr) {
    asm volatile("ldmatrix.sync.aligned.m8n8.x4.shared.b16 {%0,%1,%2,%3}, [%4];"
                 : "=r"(r0), "=r"(r1), "=r"(r2), "=r"(r3) : "r"(addr));
}

// fp16 MMA, fp32 accumulate (sm_80+, legal on plain sm_103 target)
__device__ __forceinline__ void mma_f16(float* c, const uint32_t* a,
                                        const uint32_t* b) {
    asm volatile(
        "mma.sync.aligned.m16n8k16.row.col.f32.f16.f16.f32 "
        "{%0,%1,%2,%3}, {%4,%5,%6,%7}, {%8,%9}, {%0,%1,%2,%3};"
        : "+f"(c[0]), "+f"(c[1]), "+f"(c[2]), "+f"(c[3])
        : "r"(a[0]), "r"(a[1]), "r"(a[2]), "r"(a[3]),
          "r"(b[0]), "r"(b[1]));
}

// streaming 8B store (output is write-once, never re-read by this grid)
__device__ __forceinline__ void stg_cs_v2(float* p, float x, float y) {
    asm volatile("st.global.cs.v2.f32 [%0], {%1, %2};"
                 :: "l"(p), "f"(x), "f"(y) : "memory");
}

// ================= fp32 -> fp16 RN pre-pass (both arrays, one launch) =======
static constexpr int NX4 = M_TOTAL * (K_TOTAL / 4);   // X float4 count
static constexpr int NW4 = N_TOTAL * (K_TOTAL / 4);   // W float4 count

__global__ void __launch_bounds__(256)
cvt_both_kernel(const float* __restrict__ X, const float* __restrict__ W) {
    int i = blockIdx.x * blockDim.x + threadIdx.x;
    int stride = gridDim.x * blockDim.x;
    for (; i < NX4 + NW4; i += stride) {
        const float4* s;
        __half* dst;
        int k;
        if (i < NX4) { s = (const float4*)X; dst = g_Xh; k = i; }
        else         { s = (const float4*)W; dst = g_Wh; k = i - NX4; }
        float4 v = s[k];
        __half2 h0 = __floats2half2_rn(v.x, v.y);
        __half2 h1 = __floats2half2_rn(v.z, v.w);
        uint2 pack = make_uint2(*(uint32_t*)&h0, *(uint32_t*)&h1);
        *(uint2*)(dst + (size_t)k * 4) = pack;
    }
}

// ================= GEMM kernel =================
__global__ void __launch_bounds__(256, 2)
qkv_gemm_kernel(float* __restrict__ out) {
    extern __shared__ __align__(1024) char smem[];
    const uint32_t sb = smem_u32(smem);
    const int tid = threadIdx.x;
    const int wid = tid >> 5;
    const int lid = tid & 31;

    // ---- tile mapping (grouped raster for L2 reuse) ----
    int bid = blockIdx.x;
    const int TPG = GROUP_M * NT;
    int g   = bid / TPG;
    int rem = bid % TPG;
    int m0g = g * GROUP_M;
    int rows = (MT - m0g) < GROUP_M ? (MT - m0g) : GROUP_M;
    int mtile = m0g + rem % rows;
    int ntile = rem / rows;
    const int m0 = mtile * TILE_M;
    const int n0 = ntile * TILE_N;

    // ---- mbarrier init: full[s] count=256 (async arrives), empty[s] count=8 ----
    const uint32_t FULLB  = sb + OFF_FULL;
    const uint32_t EMPTYB = sb + OFF_EMPTY;
    if (tid == 0) {
#pragma unroll
        for (int s = 0; s < STAGES; ++s) {
            mbar_init(FULLB  + 8u * s, 256);
            mbar_init(EMPTYB + 8u * s, 8);
        }
    }
    __syncthreads();   // only CTA-wide barrier: publish barrier init

    // ---- producer bases: 8 x 16B per thread per stage ----
    const int pr = tid >> 3;          // 0..31
    const int pj = tid & 7;           // 16B segment within 128B row
    const __half* gA0 = g_Xh + (size_t)(m0 + pr) * K_TOTAL + pj * 8;
    const __half* gB0 = g_Wh + (size_t)(n0 + pr) * K_TOTAL + pj * 8;
    const uint32_t swzA = SWZ((uint32_t)(pr * 128 + pj * 16));
    const uint32_t swzB = (uint32_t)A_TILE_BYTES + SWZ((uint32_t)(pr * 128 + pj * 16));

    auto produce_a = [&](int c, int slot) {
        uint32_t dstb = sb + SMEM_HDR + (uint32_t)slot * STAGE_BYTES;
        const __half* ga = gA0 + (size_t)c * TILE_K;
#pragma unroll
        for (int i = 0; i < 4; ++i)
            cp_async16(dstb + swzA + i * 4096u, ga + (size_t)i * 32 * K_TOTAL);
    };
    auto produce_b = [&](int c, int slot) {
        uint32_t dstb = sb + SMEM_HDR + (uint32_t)slot * STAGE_BYTES;
        const __half* gb = gB0 + (size_t)c * TILE_K;
#pragma unroll
        for (int i = 0; i < 4; ++i)
            cp_async16(dstb + swzB + i * 4096u, gb + (size_t)i * 32 * K_TOTAL);
    };

    // ---- prologue: produce chunks 0,1 (fresh empty barriers: no wait needed) ----
    produce_a(0, 0); produce_b(0, 0); cpasync_arrive_noinc(FULLB + 0);
    produce_a(1, 1); produce_b(1, 1); cpasync_arrive_noinc(FULLB + 8);

    // ---- accumulators: 8 warps (2x4), warp tile 64x32 ----
    float acc[4][4][4];
#pragma unroll
    for (int mt = 0; mt < 4; ++mt)
#pragma unroll
        for (int nt = 0; nt < 4; ++nt)
#pragma unroll
            for (int jj = 0; jj < 4; ++jj) acc[mt][nt][jj] = 0.0f;

    const int wm = wid & 1, wn = wid >> 1;
    const int mbase = wm * 64, nbase = wn * 32;
    const int qr = lid >> 2, qc = lid & 3;

    // ---- ldmatrix per-thread address offsets (swizzle folded to XOR const) ----
    uint32_t aoff[4];
    {
        int rowl = lid & 15;
        uint32_t kadd = (uint32_t)(lid >> 4) * 16u;
#pragma unroll
        for (int mt = 0; mt < 4; ++mt) {
            int row = mbase + mt * 16 + rowl;
            uint32_t cb = kadd ^ (uint32_t)((row & 7) * 16);
            aoff[mt] = (uint32_t)(row * 128) + cb;
        }
    }
    uint32_t boff[2];
    {
        int rowl = (lid & 7) + ((lid >> 4) << 3);
        uint32_t kadd = (uint32_t)((lid >> 3) & 1) * 16u;
#pragma unroll
        for (int p = 0; p < 2; ++p) {
            int row = nbase + p * 16 + rowl;
            uint32_t cb = kadd ^ (uint32_t)((row & 7) * 16);
            boff[p] = (uint32_t)A_TILE_BYTES + (uint32_t)(row * 128) + cb;
        }
    }

    // consumer cursor: slot = c%3, cph = (c/3)&1
    int slot = 0, cph = 0;
#pragma unroll 1
    for (int c = 0; c < KCHUNKS; ++c) {
        const bool do_prod = (c + 2 < KCHUNKS);
        // producer slot/phase derived from consumer cursor:
        // pc=c+2: pslot=(slot+2)%3; pph = (slot==0) ? cph : cph^1
        const int pslot = (slot == 0) ? 2 : slot - 1;
        const int pph   = (slot == 0) ? cph : (cph ^ 1);
        const uint32_t fullS  = FULLB  + 8u * slot;
        const uint32_t emptyS = EMPTYB + 8u * slot;
        const uint32_t fullP  = FULLB  + 8u * pslot;
        const uint32_t emptyP = EMPTYB + 8u * pslot;

        // wait chunk-c data: full[slot] phase (c/3) complete
        mbar_wait(fullS, (uint32_t)cph);

        const uint32_t stb = sb + SMEM_HDR + (uint32_t)slot * STAGE_BYTES;

        // kk = 0..2: load + mma, with producer spread at kk=0/1
#pragma unroll
        for (int kk = 0; kk < 3; ++kk) {
            const uint32_t kx = (uint32_t)kk * 32u;  // bits 5-6; XOR-composable
            uint32_t a[4][4], b[2][4];
            // B first (2 ops) then A (4 ops): shortest path to first HMMA
#pragma unroll
            for (int p = 0; p < 2; ++p)
                ldsm_x4(b[p][0], b[p][1], b[p][2], b[p][3],
                        stb + (boff[p] ^ kx));
#pragma unroll
            for (int mt = 0; mt < 4; ++mt)
                ldsm_x4(a[mt][0], a[mt][1], a[mt][2], a[mt][3],
                        stb + (aoff[mt] ^ kx));
#pragma unroll
            for (int mt = 0; mt < 4; ++mt)
#pragma unroll
                for (int p = 0; p < 2; ++p) {
                    mma_f16(acc[mt][2 * p],     a[mt], &b[p][0]);
                    mma_f16(acc[mt][2 * p + 1], a[mt], &b[p][2]);
                }
            // producer spread (R10 shape; R11: do NOT delay full-arrive past kk=1)
            if (kk == 0 && do_prod) {
                mbar_wait(emptyP, (uint32_t)(pph ^ 1));
                produce_a(c + 2, pslot);
            }
            if (kk == 1 && do_prod) {
                produce_b(c + 2, pslot);
                cpasync_arrive_noinc(fullP);
            }
        }

        // kk = 3: loads, then EARLY slot release (last smem reads of the slot
        // are done; arrive.release orders them), then the MMA bundle — gives
        // the producer a ~1-bundle head start on the empty-wait.
        {
            const uint32_t kx = 96u;
            uint32_t a[4][4], b[2][4];
#pragma unroll
            for (int p = 0; p < 2; ++p)
                ldsm_x4(b[p][0], b[p][1], b[p][2], b[p][3],
                        stb + (boff[p] ^ kx));
#pragma unroll
            for (int mt = 0; mt < 4; ++mt)
                ldsm_x4(a[mt][0], a[mt][1], a[mt][2], a[mt][3],
                        stb + (aoff[mt] ^ kx));

            __syncwarp();
            if (lid == 0) mbar_arrive(emptyS);

#pragma unroll
            for (int mt = 0; mt < 4; ++mt)
#pragma unroll
                for (int p = 0; p < 2; ++p) {
                    mma_f16(acc[mt][2 * p],     a[mt], &b[p][0]);
                    mma_f16(acc[mt][2 * p + 1], a[mt], &b[p][2]);
                }
        }

        if (++slot == STAGES) { slot = 0; cph ^= 1; }
    }

    // ---- epilogue: regs -> GMEM with q/k/v region remap ----
    // out column n -> region r = n>>12, elem e = n&4095; region stride M*4096
    {
        const int rgn = n0 >> 12;
        float* obase = out + (size_t)rgn * ((size_t)M_TOTAL * 4096)
                           + (size_t)m0 * 4096 + (size_t)(n0 & 4095);
#pragma unroll
        for (int mt = 0; mt < 4; ++mt) {
            int m = mbase + mt * 16 + qr;
#pragma unroll
            for (int nt = 0; nt < 4; ++nt) {
                int ncol = nbase + nt * 8 + 2 * qc;
                stg_cs_v2(obase + (size_t)m * 4096 + ncol,
                          acc[mt][nt][0], acc[mt][nt][1]);
                stg_cs_v2(obase + (size_t)(m + 8) * 4096 + ncol,
                          acc[mt][nt][2], acc[mt][nt][3]);
            }
        }
    }
}

// ================= launch =================
extern "C" void kernel_launch(void* const* d_in, const int* in_sizes, int n_in,
                              void* d_out, int out_size) {
    const float* X = (const float*)d_in[0];   // hidden_states [4,4096,4096]
    const float* W = (const float*)d_in[1];   // qkv_proj [12288,4096]
    float* out = (float*)d_out;               // q|k|v, 3 x [16384,4096]
    (void)in_sizes; (void)n_in; (void)out_size;

    cudaFuncSetAttribute(qkv_gemm_kernel,
                         cudaFuncAttributeMaxDynamicSharedMemorySize, SMEM_BYTES);

    cvt_both_kernel<<<2368, 256>>>(X, W);
    qkv_gemm_kernel<<<MT * NT, 256, SMEM_BYTES>>>(out);
}